// round 13
// baseline (speedup 1.0000x reference)
#include <cuda_runtime.h>
#include <cuda_bf16.h>
#include <cstdint>
#include <math.h>

typedef __nv_bfloat16 bf16;

#define DIMP 1025      // 2*D+1
#define KPAD 1088      // DIMP padded to multiple of 64
#define CTX  4096      // N+1
#define NSEQ 4095
#define LMBD 0.9f

// ------------------------------------------------------------------ scratch
__device__ bf16  g_Zt  [(size_t)CTX  * KPAD];  // Z^T, bf16, K-padded
__device__ bf16  g_Qb  [(size_t)DIMP * KPAD];  // Q bf16 K-padded
__device__ bf16  g_Pb  [(size_t)DIMP * KPAD];  // P bf16 K-padded
__device__ bf16  g_Wt  [(size_t)CTX  * KPAD];  // (Q Z)^T bf16 (cols >= DIMP zero)
__device__ bf16  g_Xb  [(size_t)CTX  * CTX];   // logits bf16
__device__ bf16  g_Ab  [(size_t)CTX  * CTX];   // softmax bf16, row-major
__device__ float g_PZ  [(size_t)DIMP * CTX];   // P @ Z fp32
__device__ bf16  g_PZMb[(size_t)DIMP * CTX];   // decay-scanned, bf16

// ------------------------------------------------------------------ helpers
__device__ __forceinline__ uint32_t smem_u32(const void* p) {
    uint32_t a;
    asm("{ .reg .u64 t; cvta.to.shared.u64 t, %1; cvt.u32.u64 %0, t; }" : "=r"(a) : "l"(p));
    return a;
}
__device__ __forceinline__ void ldsm_x4(uint32_t& r0, uint32_t& r1, uint32_t& r2, uint32_t& r3,
                                        uint32_t addr) {
    asm volatile("ldmatrix.sync.aligned.m8n8.x4.shared.b16 {%0,%1,%2,%3}, [%4];"
                 : "=r"(r0), "=r"(r1), "=r"(r2), "=r"(r3) : "r"(addr));
}
__device__ __forceinline__ void ldsm_x4_t(uint32_t& r0, uint32_t& r1, uint32_t& r2, uint32_t& r3,
                                          uint32_t addr) {
    asm volatile("ldmatrix.sync.aligned.m8n8.x4.trans.shared.b16 {%0,%1,%2,%3}, [%4];"
                 : "=r"(r0), "=r"(r1), "=r"(r2), "=r"(r3) : "r"(addr));
}
__device__ __forceinline__ void mma16816(float c[4], const uint32_t a[4],
                                         uint32_t b0, uint32_t b1) {
    asm volatile(
        "mma.sync.aligned.m16n8k16.row.col.f32.bf16.bf16.f32 "
        "{%0,%1,%2,%3}, {%4,%5,%6,%7}, {%8,%9}, {%0,%1,%2,%3};"
        : "+f"(c[0]), "+f"(c[1]), "+f"(c[2]), "+f"(c[3])
        : "r"(a[0]), "r"(a[1]), "r"(a[2]), "r"(a[3]), "r"(b0), "r"(b1));
}
__device__ __forceinline__ void cp16(uint32_t dst, const void* src, int valid_bytes) {
    asm volatile("cp.async.cg.shared.global [%0], [%1], 16, %2;"
                 :: "r"(dst), "l"(src), "r"(valid_bytes));
}

// ------------------------------------------------------------------ HMMA GEMM
// D[m][n] = sum_k A[m][k]*op(B); A bf16 K-major.
//  TB==0: B bf16 K-major [n][k] (ldb >= K)
//  TB==1: B bf16 row-major [k][n] (ldb = n-stride), loaded via ldmatrix.trans
// Block tile 128x128, 4 warps (2x2), warp tile 64x64, K-tile 64, 3-stage cp.async,
// register-double-buffered ldmatrix fragments. 128 thr/CTA -> 2 CTAs/SM.
// bmoff: extra m offset (for split-M launches).
// EPI 0: Cf = v ; EPI 1: Cb = bf16(n<Nvalid ? v : 0) for n<ldc ; EPI 2: Cf = Zadd + alpha*v
#define BM 128
#define BN 128
#define ROWB 144                        // 64 bf16 = 128B + 16B pad
#define ROWB_T 272                      // 128 bf16 = 256B + 16B pad
#define A_TILE (BM * ROWB)              // 18432
#define B_TILE0 (BN * ROWB)             // 18432
#define STAGE_BYTES (A_TILE + B_TILE0)  // 36864
#define NSTAGE 3
#define GEMM_SMEM (NSTAGE * STAGE_BYTES)  // 110592 -> 2 CTAs/SM

template <int EPI, int TB>
__global__ __launch_bounds__(128)
void gemm_hmma(const bf16* __restrict__ A, int lda, int Arows,
               const bf16* __restrict__ B, int ldb, int Brows,
               float* __restrict__ Cf, bf16* __restrict__ Cb, int ldc, int Nvalid,
               const float* __restrict__ Zadd, float alpha, int M, int K, int bmoff)
{
    extern __shared__ __align__(128) char smem[];
    const uint32_t sb = smem_u32(smem);
    const int tid  = threadIdx.x;
    const int lane = tid & 31;
    const int wid  = tid >> 5;
    const int wm   = (wid & 1) * 64;
    const int wn   = (wid >> 1) * 64;
    const int bm   = blockIdx.y * BM + bmoff;
    const int bn   = blockIdx.x * BN;

    float acc[4][8][4];
#pragma unroll
    for (int i = 0; i < 4; i++)
#pragma unroll
        for (int j = 0; j < 8; j++)
#pragma unroll
            for (int q = 0; q < 4; q++) acc[i][j][q] = 0.f;

    auto load_tile = [&](int kt, int buf) {
        const int k0 = kt * 64;
        const uint32_t base = sb + buf * STAGE_BYTES;
        {
            const int row = tid >> 3, ch = tid & 7;
#pragma unroll
            for (int it = 0; it < 8; it++) {
                int r = row + it * 16;
                int gr = bm + r;
                const bf16* src = A + (size_t)min(gr, Arows - 1) * lda + k0 + ch * 8;
                cp16(base + r * ROWB + ch * 16, src, gr < Arows ? 16 : 0);
            }
        }
        const uint32_t baseB = base + A_TILE;
        if (TB == 0) {
            const int row = tid >> 3, ch = tid & 7;
#pragma unroll
            for (int it = 0; it < 8; it++) {
                int r = row + it * 16;
                int gr = bn + r;
                const bf16* src = B + (size_t)min(gr, Brows - 1) * ldb + k0 + ch * 8;
                cp16(baseB + r * ROWB + ch * 16, src, gr < Brows ? 16 : 0);
            }
        } else {
#pragma unroll
            for (int it = 0; it < 8; it++) {
                int idx = tid + it * 128;
                int r = idx >> 4, ch = idx & 15;
                const bf16* src = B + (size_t)(k0 + r) * ldb + bn + ch * 8;
                cp16(baseB + r * ROWB_T + ch * 16, src, 16);
            }
        }
        asm volatile("cp.async.commit_group;" ::: "memory");
    };

    const int KT = K / 64;
    load_tile(0, 0);
    if (KT > 1) load_tile(1, 1);

    const int a_row = wm + (lane & 15);
    const int a_kof = (lane >> 4) << 3;
    const int b_row = wn + ((lane >> 4) << 3) + (lane & 7);   // TB=0
    const int b_kof = lane & 8;
    const int t_row = (lane & 7) + 8 * ((lane >> 3) & 1);     // TB=1
    const int t_col = wn + ((lane >> 4) << 3);

    uint32_t fa[2][4][4], fb[2][4][4];

    for (int kt = 0; kt < KT; kt++) {
        if (kt + 1 < KT) asm volatile("cp.async.wait_group 1;" ::: "memory");
        else             asm volatile("cp.async.wait_group 0;" ::: "memory");
        __syncthreads();
        if (kt + 2 < KT) load_tile(kt + 2, (kt + 2) % NSTAGE);

        const uint32_t Ab_s = sb + (kt % NSTAGE) * STAGE_BYTES;
        const uint32_t Bb_s = Ab_s + A_TILE;

#pragma unroll
        for (int mf = 0; mf < 4; mf++)
            ldsm_x4(fa[0][mf][0], fa[0][mf][1], fa[0][mf][2], fa[0][mf][3],
                    Ab_s + (a_row + mf * 16) * ROWB + a_kof * 2);
#pragma unroll
        for (int g = 0; g < 4; g++) {
            if (TB == 0)
                ldsm_x4(fb[0][g][0], fb[0][g][1], fb[0][g][2], fb[0][g][3],
                        Bb_s + (b_row + g * 16) * ROWB + b_kof * 2);
            else
                ldsm_x4_t(fb[0][g][0], fb[0][g][1], fb[0][g][2], fb[0][g][3],
                          Bb_s + t_row * ROWB_T + (t_col + g * 16) * 2);
        }

#pragma unroll
        for (int ks = 0; ks < 4; ks++) {
            const int cur = ks & 1, nxt = cur ^ 1;
            if (ks < 3) {
                const int k = (ks + 1) * 16;
#pragma unroll
                for (int mf = 0; mf < 4; mf++)
                    ldsm_x4(fa[nxt][mf][0], fa[nxt][mf][1], fa[nxt][mf][2], fa[nxt][mf][3],
                            Ab_s + (a_row + mf * 16) * ROWB + (k + a_kof) * 2);
#pragma unroll
                for (int g = 0; g < 4; g++) {
                    if (TB == 0)
                        ldsm_x4(fb[nxt][g][0], fb[nxt][g][1], fb[nxt][g][2], fb[nxt][g][3],
                                Bb_s + (b_row + g * 16) * ROWB + (k + b_kof) * 2);
                    else
                        ldsm_x4_t(fb[nxt][g][0], fb[nxt][g][1], fb[nxt][g][2], fb[nxt][g][3],
                                  Bb_s + (k + t_row) * ROWB_T + (t_col + g * 16) * 2);
                }
            }
#pragma unroll
            for (int g = 0; g < 4; g++)
#pragma unroll
                for (int mf = 0; mf < 4; mf++) {
                    mma16816(acc[mf][2 * g + 0], fa[cur][mf], fb[cur][g][0], fb[cur][g][1]);
                    mma16816(acc[mf][2 * g + 1], fa[cur][mf], fb[cur][g][2], fb[cur][g][3]);
                }
        }
    }

    // ---------------- epilogue ----------------
    const int gid = lane >> 2;
    const int tg  = lane & 3;
#pragma unroll
    for (int mf = 0; mf < 4; mf++) {
#pragma unroll
        for (int half = 0; half < 2; half++) {
            const int gm = bm + wm + mf * 16 + gid + half * 8;
            if (gm >= M) continue;
#pragma unroll
            for (int nf = 0; nf < 8; nf++) {
                const int gn = bn + wn + nf * 8 + 2 * tg;
                float v0 = acc[mf][nf][2 * half + 0];
                float v1 = acc[mf][nf][2 * half + 1];
                if (EPI == 0) {
                    *(float2*)(Cf + (size_t)gm * ldc + gn) = make_float2(v0, v1);
                } else if (EPI == 1) {
                    if (gn < ldc) {
                        if (gn >= Nvalid)     v0 = 0.f;
                        if (gn + 1 >= Nvalid) v1 = 0.f;
                        *(__nv_bfloat162*)(Cb + (size_t)gm * ldc + gn) =
                            __floats2bfloat162_rn(v0, v1);
                    }
                } else {
                    const float2 z = *(const float2*)(Zadd + (size_t)gm * ldc + gn);
                    *(float2*)(Cf + (size_t)gm * ldc + gn) =
                        make_float2(fmaf(alpha, v0, z.x), fmaf(alpha, v1, z.y));
                }
            }
        }
    }
}

// ------------------------------------------------------------------ prep kernels
__global__ __launch_bounds__(256)
void convQP(const float* __restrict__ Qf, const float* __restrict__ Pf)
{
    int idx = blockIdx.x * 256 + threadIdx.x;
    if (idx >= DIMP * KPAD) return;
    int r = idx / KPAD, c = idx % KPAD;
    float q = (c < DIMP) ? Qf[(size_t)r * DIMP + c] : 0.f;
    float p = (c < DIMP) ? Pf[(size_t)r * DIMP + c] : 0.f;
    g_Qb[idx] = __float2bfloat16(q);
    g_Pb[idx] = __float2bfloat16(p);
}

__global__ __launch_bounds__(256)
void transpose_conv(const float* __restrict__ in, bf16* __restrict__ out,
                    int R, int C, int ldo)
{
    __shared__ float t[32][33];
    int tx = threadIdx.x, ty = threadIdx.y;
    int gc = blockIdx.x * 32 + tx;
#pragma unroll
    for (int i = 0; i < 32; i += 8) {
        int gr = blockIdx.y * 32 + ty + i;
        t[ty + i][tx] = (gr < R) ? in[(size_t)gr * C + gc] : 0.f;
    }
    __syncthreads();
#pragma unroll
    for (int i = 0; i < 32; i += 8) {
        int oc = blockIdx.x * 32 + ty + i;
        int orr = blockIdx.y * 32 + tx;
        if (orr < ldo)
            out[(size_t)oc * ldo + orr] = __float2bfloat16(t[tx][ty + i]);
    }
}

// ------------------------------------------------------------------ softmax: A = softmax(Xb) rows, bf16 in/out
__global__ __launch_bounds__(256)
void softmax_bf16(const bf16* __restrict__ X, bf16* __restrict__ A)
{
    __shared__ float red[8];
    const int row = blockIdx.x;
    const int tid = threadIdx.x;
    const uint4* src = (const uint4*)(X + (size_t)row * CTX + tid * 16);

    uint4 raw[2];
    raw[0] = src[0];
    raw[1] = src[1];
    const __nv_bfloat162* bp = (const __nv_bfloat162*)raw;
    float v[16];
#pragma unroll
    for (int i = 0; i < 8; i++) {
        float2 f = __bfloat1622float2(bp[i]);
        v[2 * i] = f.x; v[2 * i + 1] = f.y;
    }

    float mx = -1e30f;
#pragma unroll
    for (int i = 0; i < 16; i++) mx = fmaxf(mx, v[i]);
#pragma unroll
    for (int o = 16; o; o >>= 1) mx = fmaxf(mx, __shfl_xor_sync(0xffffffffu, mx, o));
    if ((tid & 31) == 0) red[tid >> 5] = mx;
    __syncthreads();
    mx = red[0];
#pragma unroll
    for (int i = 1; i < 8; i++) mx = fmaxf(mx, red[i]);
    __syncthreads();

    float s = 0.f;
#pragma unroll
    for (int i = 0; i < 16; i++) { v[i] = __expf(v[i] - mx); s += v[i]; }
#pragma unroll
    for (int o = 16; o; o >>= 1) s += __shfl_xor_sync(0xffffffffu, s, o);
    if ((tid & 31) == 0) red[tid >> 5] = s;
    __syncthreads();
    s = red[0];
#pragma unroll
    for (int i = 1; i < 8; i++) s += red[i];
    const float inv = 1.f / s;

    __nv_bfloat162* dst = (__nv_bfloat162*)(A + (size_t)row * CTX + tid * 16);
#pragma unroll
    for (int i = 0; i < 8; i++)
        dst[i] = __floats2bfloat162_rn(v[2 * i] * inv, v[2 * i + 1] * inv);
}

// ------------------------------------------------------------------ decay suffix SCAN
__global__ __launch_bounds__(256)
void decay_scan(const float* __restrict__ PZ, bf16* __restrict__ PZMb)
{
    const int d    = blockIdx.x;
    const int tid  = threadIdx.x;
    const int lane = tid & 31;
    const int w    = tid >> 5;
    const float* row = PZ + (size_t)d * CTX;

    float x[16];
    const float4* src = (const float4*)(row + tid * 16);
#pragma unroll
    for (int i = 0; i < 4; i++) {
        float4 v = src[i];
        x[4 * i] = v.x; x[4 * i + 1] = v.y; x[4 * i + 2] = v.z; x[4 * i + 3] = v.w;
    }
    if (tid == 255) x[15] = 0.f;    // n = NSEQ (4095): M's last row is zero

    float local[16];
    float r = 0.f;
#pragma unroll
    for (int j = 15; j >= 0; j--) { r = fmaf(LMBD, r, x[j]); local[j] = r; }

    const float d16 = 0.185302018885184100f;   // 0.9^16
    float F = local[0];
    float f = d16;
#pragma unroll
    for (int off = 1; off < 32; off <<= 1) {
        float nb = __shfl_down_sync(0xffffffffu, F, off);
        if (lane + off < 32) F = fmaf(f, nb, F);
        f *= f;
    }

    __shared__ float wsum[8];
    if (lane == 0) wsum[w] = F;
    __syncthreads();
    const float Tw = (w < 7) ? wsum[w + 1] : 0.f;
    F = fmaf(__powf(d16, (float)(32 - lane)), Tw, F);

    float G = __shfl_down_sync(0xffffffffu, F, 1);
    if (lane == 31) G = Tw;

    float wgt[16];
    float pw = LMBD;
#pragma unroll
    for (int j = 15; j >= 0; j--) { wgt[j] = pw; pw *= LMBD; }

    __nv_bfloat162* dst = (__nv_bfloat162*)(PZMb + (size_t)d * CTX + tid * 16);
#pragma unroll
    for (int i = 0; i < 8; i++) {
        float v0 = fmaf(wgt[2 * i + 0], G, local[2 * i + 0]);
        float v1 = fmaf(wgt[2 * i + 1], G, local[2 * i + 1]);
        dst[i] = __floats2bfloat162_rn(v0, v1);
    }
}

// ------------------------------------------------------------------ stream/event resources
namespace {
struct SideRes {
    cudaStream_t s2;
    cudaEvent_t evFork, evT, evQP, evA, evSa, evJoin;
    SideRes() {
        cudaStreamCreateWithFlags(&s2, cudaStreamNonBlocking);
        cudaEventCreateWithFlags(&evFork, cudaEventDisableTiming);
        cudaEventCreateWithFlags(&evT,    cudaEventDisableTiming);
        cudaEventCreateWithFlags(&evQP,   cudaEventDisableTiming);
        cudaEventCreateWithFlags(&evA,    cudaEventDisableTiming);
        cudaEventCreateWithFlags(&evSa,   cudaEventDisableTiming);
        cudaEventCreateWithFlags(&evJoin, cudaEventDisableTiming);
    }
};
SideRes& side() { static SideRes r; return r; }
}

// ------------------------------------------------------------------ launch
extern "C" void kernel_launch(void* const* d_in, const int* in_sizes, int n_in,
                              void* d_out, int out_size)
{
    const float* Z = (const float*)d_in[0];   // (1025, 4096)
    const float* P = (const float*)d_in[1];   // (1025, 1025)
    const float* Q = (const float*)d_in[2];   // (1025, 1025)
    float* out = (float*)d_out;               // (1025, 4096)

    bf16 *Zt, *Qb, *Pb, *Wt, *Xb, *Ab, *PZMb;
    float *PZ;
    cudaGetSymbolAddress((void**)&Zt, g_Zt);
    cudaGetSymbolAddress((void**)&Qb, g_Qb);
    cudaGetSymbolAddress((void**)&Pb, g_Pb);
    cudaGetSymbolAddress((void**)&Wt, g_Wt);
    cudaGetSymbolAddress((void**)&Xb, g_Xb);
    cudaGetSymbolAddress((void**)&Ab, g_Ab);
    cudaGetSymbolAddress((void**)&PZ, g_PZ);
    cudaGetSymbolAddress((void**)&PZMb, g_PZMb);

    cudaFuncSetAttribute(gemm_hmma<0,0>, cudaFuncAttributeMaxDynamicSharedMemorySize, GEMM_SMEM);
    cudaFuncSetAttribute(gemm_hmma<1,0>, cudaFuncAttributeMaxDynamicSharedMemorySize, GEMM_SMEM);
    cudaFuncSetAttribute(gemm_hmma<2,1>, cudaFuncAttributeMaxDynamicSharedMemorySize, GEMM_SMEM);

    SideRes& r = side();

    // Fork FIRST (capture-legal: s2 enters capture via an event recorded on the
    // capturing stream before any launch on s2).
    cudaEventRecord(r.evFork, 0);
    cudaStreamWaitEvent(r.s2, r.evFork, 0);

    // side: Q/P conversion. main: Z transpose. (independent)
    convQP<<<(DIMP * KPAD + 255) / 256, 256, 0, r.s2>>>(Q, P);
    cudaEventRecord(r.evQP, r.s2);
    transpose_conv<<<dim3(CTX / 32, KPAD / 32), dim3(32, 8)>>>(Z, Zt, DIMP, CTX, KPAD);
    cudaEventRecord(r.evT, 0);

    // side branch: PZ = P @ Z -> decay scan (needs Zt from main; Pb local to s2)
    cudaStreamWaitEvent(r.s2, r.evT, 0);
    gemm_hmma<0,0><<<dim3(CTX / BN, (DIMP + BM - 1) / BM), 128, GEMM_SMEM, r.s2>>>(
        Pb, KPAD, DIMP, Zt, KPAD, CTX, PZ, nullptr, CTX, CTX,
        nullptr, 0.f, DIMP, KPAD, 0);
    decay_scan<<<DIMP, 256, 0, r.s2>>>(PZ, PZMb);
    cudaEventRecord(r.evJoin, r.s2);

    // main branch (needs Qb from s2)
    cudaStreamWaitEvent(0, r.evQP, 0);
    // 1) Wt[n][d] = sum_k Zt[n][k] * Qb[d][k]   ((QZ)^T bf16, cols>=DIMP zeroed)
    gemm_hmma<1,0><<<dim3((KPAD + BN - 1) / BN, CTX / BM), 128, GEMM_SMEM>>>(
        Zt, KPAD, CTX, Qb, KPAD, DIMP, nullptr, Wt, KPAD, DIMP,
        nullptr, 0.f, CTX, KPAD, 0);
    // 2a) Xb rows [0, 2048)
    gemm_hmma<1,0><<<dim3(CTX / BN, 16), 128, GEMM_SMEM>>>(
        Zt, KPAD, CTX, Wt, KPAD, CTX, nullptr, Xb, CTX, CTX,
        nullptr, 0.f, CTX, KPAD, 0);
    cudaEventRecord(r.evA, 0);
    // 2b) Xb rows [2048, 4096) — overlaps softmax_a on s2
    gemm_hmma<1,0><<<dim3(CTX / BN, 16), 128, GEMM_SMEM>>>(
        Zt, KPAD, CTX, Wt, KPAD, CTX, nullptr, Xb, CTX, CTX,
        nullptr, 0.f, CTX, KPAD, 2048);

    // softmax first half on side stream, concurrent with GEMM2b
    cudaStreamWaitEvent(r.s2, r.evA, 0);
    softmax_bf16<<<2048, 256, 0, r.s2>>>(Xb, Ab);
    cudaEventRecord(r.evSa, r.s2);

    // softmax second half on main
    softmax_bf16<<<2048, 256>>>(Xb + (size_t)2048 * CTX, Ab + (size_t)2048 * CTX);

    // join, then final GEMM
    cudaStreamWaitEvent(0, r.evSa, 0);
    cudaStreamWaitEvent(0, r.evJoin, 0);
    // 3) out[d][c] = Z[d][c] + (1/N) * sum_k PZMb[d][k] * Ab[k][c]
    gemm_hmma<2,1><<<dim3(CTX / BN, (DIMP + BM - 1) / BM), 128, GEMM_SMEM>>>(
        PZMb, CTX, DIMP, Ab, CTX, CTX, out, nullptr, CTX, CTX,
        Z, 1.0f / (float)NSEQ, DIMP, CTX, 0);
}

// round 14
// speedup vs baseline: 1.0704x; 1.0704x over previous
#include <cuda_runtime.h>
#include <cuda_bf16.h>
#include <cstdint>
#include <math.h>

typedef __nv_bfloat16 bf16;

#define DIMP 1025      // 2*D+1
#define KPAD 1088      // DIMP padded to multiple of 64
#define CTX  4096      // N+1
#define NSEQ 4095
#define LMBD 0.9f

// ------------------------------------------------------------------ scratch
__device__ bf16  g_Zt  [(size_t)CTX  * KPAD];  // Z^T, bf16, K-padded
__device__ bf16  g_Qb  [(size_t)DIMP * KPAD];  // Q bf16 K-padded
__device__ bf16  g_Pb  [(size_t)DIMP * KPAD];  // P bf16 K-padded
__device__ bf16  g_Wt  [(size_t)CTX  * KPAD];  // (Q Z)^T bf16 (cols >= DIMP zero)
__device__ bf16  g_Xb  [(size_t)CTX  * CTX];   // logits bf16
__device__ bf16  g_Ab  [(size_t)CTX  * CTX];   // softmax bf16, row-major
__device__ float g_PZ  [(size_t)DIMP * CTX];   // P @ Z fp32
__device__ bf16  g_PZMb[(size_t)DIMP * CTX];   // decay-scanned, bf16

// ------------------------------------------------------------------ helpers
__device__ __forceinline__ uint32_t smem_u32(const void* p) {
    uint32_t a;
    asm("{ .reg .u64 t; cvta.to.shared.u64 t, %1; cvt.u32.u64 %0, t; }" : "=r"(a) : "l"(p));
    return a;
}
__device__ __forceinline__ void ldsm_x4(uint32_t& r0, uint32_t& r1, uint32_t& r2, uint32_t& r3,
                                        uint32_t addr) {
    asm volatile("ldmatrix.sync.aligned.m8n8.x4.shared.b16 {%0,%1,%2,%3}, [%4];"
                 : "=r"(r0), "=r"(r1), "=r"(r2), "=r"(r3) : "r"(addr));
}
__device__ __forceinline__ void ldsm_x4_t(uint32_t& r0, uint32_t& r1, uint32_t& r2, uint32_t& r3,
                                          uint32_t addr) {
    asm volatile("ldmatrix.sync.aligned.m8n8.x4.trans.shared.b16 {%0,%1,%2,%3}, [%4];"
                 : "=r"(r0), "=r"(r1), "=r"(r2), "=r"(r3) : "r"(addr));
}
__device__ __forceinline__ void mma16816(float c[4], const uint32_t a[4],
                                         uint32_t b0, uint32_t b1) {
    asm volatile(
        "mma.sync.aligned.m16n8k16.row.col.f32.bf16.bf16.f32 "
        "{%0,%1,%2,%3}, {%4,%5,%6,%7}, {%8,%9}, {%0,%1,%2,%3};"
        : "+f"(c[0]), "+f"(c[1]), "+f"(c[2]), "+f"(c[3])
        : "r"(a[0]), "r"(a[1]), "r"(a[2]), "r"(a[3]), "r"(b0), "r"(b1));
}
__device__ __forceinline__ void cp16(uint32_t dst, const void* src, int valid_bytes) {
    asm volatile("cp.async.cg.shared.global [%0], [%1], 16, %2;"
                 :: "r"(dst), "l"(src), "r"(valid_bytes));
}

// ------------------------------------------------------------------ HMMA GEMM
// D[m][n] = sum_k A[m][k]*op(B); A bf16 K-major.
//  TB==0: B bf16 K-major [n][k] (ldb >= K)
//  TB==1: B bf16 row-major [k][n] (ldb = n-stride), loaded via ldmatrix.trans
// Block tile 128x128, 4 warps (2x2), warp tile 64x64, K-tile 64, 3-stage cp.async,
// register-double-buffered ldmatrix fragments. 128 thr/CTA -> 2 CTAs/SM.
// EPI 0: Cf = v ; EPI 1: Cb = bf16(n<Nvalid ? v : 0) for n<ldc ; EPI 2: Cf = Zadd + alpha*v
#define BM 128
#define BN 128
#define ROWB 144                        // 64 bf16 = 128B + 16B pad
#define ROWB_T 272                      // 128 bf16 = 256B + 16B pad
#define A_TILE (BM * ROWB)              // 18432
#define B_TILE0 (BN * ROWB)             // 18432
#define STAGE_BYTES (A_TILE + B_TILE0)  // 36864
#define NSTAGE 3
#define GEMM_SMEM (NSTAGE * STAGE_BYTES)  // 110592 -> 2 CTAs/SM

template <int EPI, int TB>
__global__ __launch_bounds__(128)
void gemm_hmma(const bf16* __restrict__ A, int lda, int Arows,
               const bf16* __restrict__ B, int ldb, int Brows,
               float* __restrict__ Cf, bf16* __restrict__ Cb, int ldc, int Nvalid,
               const float* __restrict__ Zadd, float alpha, int M, int K)
{
    extern __shared__ __align__(128) char smem[];
    const uint32_t sb = smem_u32(smem);
    const int tid  = threadIdx.x;
    const int lane = tid & 31;
    const int wid  = tid >> 5;
    const int wm   = (wid & 1) * 64;
    const int wn   = (wid >> 1) * 64;
    const int bm   = blockIdx.y * BM;
    const int bn   = blockIdx.x * BN;

    float acc[4][8][4];
#pragma unroll
    for (int i = 0; i < 4; i++)
#pragma unroll
        for (int j = 0; j < 8; j++)
#pragma unroll
            for (int q = 0; q < 4; q++) acc[i][j][q] = 0.f;

    auto load_tile = [&](int kt, int buf) {
        const int k0 = kt * 64;
        const uint32_t base = sb + buf * STAGE_BYTES;
        {
            const int row = tid >> 3, ch = tid & 7;
#pragma unroll
            for (int it = 0; it < 8; it++) {
                int r = row + it * 16;
                int gr = bm + r;
                const bf16* src = A + (size_t)min(gr, Arows - 1) * lda + k0 + ch * 8;
                cp16(base + r * ROWB + ch * 16, src, gr < Arows ? 16 : 0);
            }
        }
        const uint32_t baseB = base + A_TILE;
        if (TB == 0) {
            const int row = tid >> 3, ch = tid & 7;
#pragma unroll
            for (int it = 0; it < 8; it++) {
                int r = row + it * 16;
                int gr = bn + r;
                const bf16* src = B + (size_t)min(gr, Brows - 1) * ldb + k0 + ch * 8;
                cp16(baseB + r * ROWB + ch * 16, src, gr < Brows ? 16 : 0);
            }
        } else {
#pragma unroll
            for (int it = 0; it < 8; it++) {
                int idx = tid + it * 128;
                int r = idx >> 4, ch = idx & 15;
                const bf16* src = B + (size_t)(k0 + r) * ldb + bn + ch * 8;
                cp16(baseB + r * ROWB_T + ch * 16, src, 16);
            }
        }
        asm volatile("cp.async.commit_group;" ::: "memory");
    };

    const int KT = K / 64;
    load_tile(0, 0);
    if (KT > 1) load_tile(1, 1);

    const int a_row = wm + (lane & 15);
    const int a_kof = (lane >> 4) << 3;
    const int b_row = wn + ((lane >> 4) << 3) + (lane & 7);   // TB=0
    const int b_kof = lane & 8;
    const int t_row = (lane & 7) + 8 * ((lane >> 3) & 1);     // TB=1
    const int t_col = wn + ((lane >> 4) << 3);

    uint32_t fa[2][4][4], fb[2][4][4];

    for (int kt = 0; kt < KT; kt++) {
        if (kt + 1 < KT) asm volatile("cp.async.wait_group 1;" ::: "memory");
        else             asm volatile("cp.async.wait_group 0;" ::: "memory");
        __syncthreads();
        if (kt + 2 < KT) load_tile(kt + 2, (kt + 2) % NSTAGE);

        const uint32_t Ab_s = sb + (kt % NSTAGE) * STAGE_BYTES;
        const uint32_t Bb_s = Ab_s + A_TILE;

#pragma unroll
        for (int mf = 0; mf < 4; mf++)
            ldsm_x4(fa[0][mf][0], fa[0][mf][1], fa[0][mf][2], fa[0][mf][3],
                    Ab_s + (a_row + mf * 16) * ROWB + a_kof * 2);
#pragma unroll
        for (int g = 0; g < 4; g++) {
            if (TB == 0)
                ldsm_x4(fb[0][g][0], fb[0][g][1], fb[0][g][2], fb[0][g][3],
                        Bb_s + (b_row + g * 16) * ROWB + b_kof * 2);
            else
                ldsm_x4_t(fb[0][g][0], fb[0][g][1], fb[0][g][2], fb[0][g][3],
                          Bb_s + t_row * ROWB_T + (t_col + g * 16) * 2);
        }

#pragma unroll
        for (int ks = 0; ks < 4; ks++) {
            const int cur = ks & 1, nxt = cur ^ 1;
            if (ks < 3) {
                const int k = (ks + 1) * 16;
#pragma unroll
                for (int mf = 0; mf < 4; mf++)
                    ldsm_x4(fa[nxt][mf][0], fa[nxt][mf][1], fa[nxt][mf][2], fa[nxt][mf][3],
                            Ab_s + (a_row + mf * 16) * ROWB + (k + a_kof) * 2);
#pragma unroll
                for (int g = 0; g < 4; g++) {
                    if (TB == 0)
                        ldsm_x4(fb[nxt][g][0], fb[nxt][g][1], fb[nxt][g][2], fb[nxt][g][3],
                                Bb_s + (b_row + g * 16) * ROWB + (k + b_kof) * 2);
                    else
                        ldsm_x4_t(fb[nxt][g][0], fb[nxt][g][1], fb[nxt][g][2], fb[nxt][g][3],
                                  Bb_s + (k + t_row) * ROWB_T + (t_col + g * 16) * 2);
                }
            }
#pragma unroll
            for (int g = 0; g < 4; g++)
#pragma unroll
                for (int mf = 0; mf < 4; mf++) {
                    mma16816(acc[mf][2 * g + 0], fa[cur][mf], fb[cur][g][0], fb[cur][g][1]);
                    mma16816(acc[mf][2 * g + 1], fa[cur][mf], fb[cur][g][2], fb[cur][g][3]);
                }
        }
    }

    // ---------------- epilogue ----------------
    const int gid = lane >> 2;
    const int tg  = lane & 3;
#pragma unroll
    for (int mf = 0; mf < 4; mf++) {
#pragma unroll
        for (int half = 0; half < 2; half++) {
            const int gm = bm + wm + mf * 16 + gid + half * 8;
            if (gm >= M) continue;
#pragma unroll
            for (int nf = 0; nf < 8; nf++) {
                const int gn = bn + wn + nf * 8 + 2 * tg;
                float v0 = acc[mf][nf][2 * half + 0];
                float v1 = acc[mf][nf][2 * half + 1];
                if (EPI == 0) {
                    *(float2*)(Cf + (size_t)gm * ldc + gn) = make_float2(v0, v1);
                } else if (EPI == 1) {
                    if (gn < ldc) {
                        if (gn >= Nvalid)     v0 = 0.f;
                        if (gn + 1 >= Nvalid) v1 = 0.f;
                        *(__nv_bfloat162*)(Cb + (size_t)gm * ldc + gn) =
                            __floats2bfloat162_rn(v0, v1);
                    }
                } else {
                    const float2 z = *(const float2*)(Zadd + (size_t)gm * ldc + gn);
                    *(float2*)(Cf + (size_t)gm * ldc + gn) =
                        make_float2(fmaf(alpha, v0, z.x), fmaf(alpha, v1, z.y));
                }
            }
        }
    }
}

// ------------------------------------------------------------------ prep kernels
__global__ __launch_bounds__(256)
void convQP(const float* __restrict__ Qf, const float* __restrict__ Pf)
{
    int idx = blockIdx.x * 256 + threadIdx.x;
    if (idx >= DIMP * KPAD) return;
    int r = idx / KPAD, c = idx % KPAD;
    float q = (c < DIMP) ? Qf[(size_t)r * DIMP + c] : 0.f;
    float p = (c < DIMP) ? Pf[(size_t)r * DIMP + c] : 0.f;
    g_Qb[idx] = __float2bfloat16(q);
    g_Pb[idx] = __float2bfloat16(p);
}

__global__ __launch_bounds__(256)
void transpose_conv(const float* __restrict__ in, bf16* __restrict__ out,
                    int R, int C, int ldo)
{
    __shared__ float t[32][33];
    int tx = threadIdx.x, ty = threadIdx.y;
    int gc = blockIdx.x * 32 + tx;
#pragma unroll
    for (int i = 0; i < 32; i += 8) {
        int gr = blockIdx.y * 32 + ty + i;
        t[ty + i][tx] = (gr < R) ? in[(size_t)gr * C + gc] : 0.f;
    }
    __syncthreads();
#pragma unroll
    for (int i = 0; i < 32; i += 8) {
        int oc = blockIdx.x * 32 + ty + i;
        int orr = blockIdx.y * 32 + tx;
        if (orr < ldo)
            out[(size_t)oc * ldo + orr] = __float2bfloat16(t[tx][ty + i]);
    }
}

// ------------------------------------------------------------------ softmax: A = softmax(Xb) rows, bf16 in/out
__global__ __launch_bounds__(256)
void softmax_bf16(const bf16* __restrict__ X, bf16* __restrict__ A)
{
    __shared__ float red[8];
    const int row = blockIdx.x;
    const int tid = threadIdx.x;
    const uint4* src = (const uint4*)(X + (size_t)row * CTX + tid * 16);

    uint4 raw[2];
    raw[0] = src[0];
    raw[1] = src[1];
    const __nv_bfloat162* bp = (const __nv_bfloat162*)raw;
    float v[16];
#pragma unroll
    for (int i = 0; i < 8; i++) {
        float2 f = __bfloat1622float2(bp[i]);
        v[2 * i] = f.x; v[2 * i + 1] = f.y;
    }

    float mx = -1e30f;
#pragma unroll
    for (int i = 0; i < 16; i++) mx = fmaxf(mx, v[i]);
#pragma unroll
    for (int o = 16; o; o >>= 1) mx = fmaxf(mx, __shfl_xor_sync(0xffffffffu, mx, o));
    if ((tid & 31) == 0) red[tid >> 5] = mx;
    __syncthreads();
    mx = red[0];
#pragma unroll
    for (int i = 1; i < 8; i++) mx = fmaxf(mx, red[i]);
    __syncthreads();

    float s = 0.f;
#pragma unroll
    for (int i = 0; i < 16; i++) { v[i] = __expf(v[i] - mx); s += v[i]; }
#pragma unroll
    for (int o = 16; o; o >>= 1) s += __shfl_xor_sync(0xffffffffu, s, o);
    if ((tid & 31) == 0) red[tid >> 5] = s;
    __syncthreads();
    s = red[0];
#pragma unroll
    for (int i = 1; i < 8; i++) s += red[i];
    const float inv = 1.f / s;

    __nv_bfloat162* dst = (__nv_bfloat162*)(A + (size_t)row * CTX + tid * 16);
#pragma unroll
    for (int i = 0; i < 8; i++)
        dst[i] = __floats2bfloat162_rn(v[2 * i] * inv, v[2 * i + 1] * inv);
}

// ------------------------------------------------------------------ decay suffix SCAN
__global__ __launch_bounds__(256)
void decay_scan(const float* __restrict__ PZ, bf16* __restrict__ PZMb)
{
    const int d    = blockIdx.x;
    const int tid  = threadIdx.x;
    const int lane = tid & 31;
    const int w    = tid >> 5;
    const float* row = PZ + (size_t)d * CTX;

    float x[16];
    const float4* src = (const float4*)(row + tid * 16);
#pragma unroll
    for (int i = 0; i < 4; i++) {
        float4 v = src[i];
        x[4 * i] = v.x; x[4 * i + 1] = v.y; x[4 * i + 2] = v.z; x[4 * i + 3] = v.w;
    }
    if (tid == 255) x[15] = 0.f;    // n = NSEQ (4095): M's last row is zero

    float local[16];
    float r = 0.f;
#pragma unroll
    for (int j = 15; j >= 0; j--) { r = fmaf(LMBD, r, x[j]); local[j] = r; }

    const float d16 = 0.185302018885184100f;   // 0.9^16
    float F = local[0];
    float f = d16;
#pragma unroll
    for (int off = 1; off < 32; off <<= 1) {
        float nb = __shfl_down_sync(0xffffffffu, F, off);
        if (lane + off < 32) F = fmaf(f, nb, F);
        f *= f;
    }

    __shared__ float wsum[8];
    if (lane == 0) wsum[w] = F;
    __syncthreads();
    const float Tw = (w < 7) ? wsum[w + 1] : 0.f;
    F = fmaf(__powf(d16, (float)(32 - lane)), Tw, F);

    float G = __shfl_down_sync(0xffffffffu, F, 1);
    if (lane == 31) G = Tw;

    float wgt[16];
    float pw = LMBD;
#pragma unroll
    for (int j = 15; j >= 0; j--) { wgt[j] = pw; pw *= LMBD; }

    __nv_bfloat162* dst = (__nv_bfloat162*)(PZMb + (size_t)d * CTX + tid * 16);
#pragma unroll
    for (int i = 0; i < 8; i++) {
        float v0 = fmaf(wgt[2 * i + 0], G, local[2 * i + 0]);
        float v1 = fmaf(wgt[2 * i + 1], G, local[2 * i + 1]);
        dst[i] = __floats2bfloat162_rn(v0, v1);
    }
}

// ------------------------------------------------------------------ stream/event resources
namespace {
struct SideRes {
    cudaStream_t s2;
    cudaEvent_t evFork, evQP, evJoin;
    SideRes() {
        cudaStreamCreateWithFlags(&s2, cudaStreamNonBlocking);
        cudaEventCreateWithFlags(&evFork, cudaEventDisableTiming);
        cudaEventCreateWithFlags(&evQP,   cudaEventDisableTiming);
        cudaEventCreateWithFlags(&evJoin, cudaEventDisableTiming);
    }
};
SideRes& side() { static SideRes r; return r; }
}

// ------------------------------------------------------------------ launch
extern "C" void kernel_launch(void* const* d_in, const int* in_sizes, int n_in,
                              void* d_out, int out_size)
{
    const float* Z = (const float*)d_in[0];   // (1025, 4096)
    const float* P = (const float*)d_in[1];   // (1025, 1025)
    const float* Q = (const float*)d_in[2];   // (1025, 1025)
    float* out = (float*)d_out;               // (1025, 4096)

    bf16 *Zt, *Qb, *Pb, *Wt, *Xb, *Ab, *PZMb;
    float *PZ;
    cudaGetSymbolAddress((void**)&Zt, g_Zt);
    cudaGetSymbolAddress((void**)&Qb, g_Qb);
    cudaGetSymbolAddress((void**)&Pb, g_Pb);
    cudaGetSymbolAddress((void**)&Wt, g_Wt);
    cudaGetSymbolAddress((void**)&Xb, g_Xb);
    cudaGetSymbolAddress((void**)&Ab, g_Ab);
    cudaGetSymbolAddress((void**)&PZ, g_PZ);
    cudaGetSymbolAddress((void**)&PZMb, g_PZMb);

    cudaFuncSetAttribute(gemm_hmma<0,0>, cudaFuncAttributeMaxDynamicSharedMemorySize, GEMM_SMEM);
    cudaFuncSetAttribute(gemm_hmma<1,0>, cudaFuncAttributeMaxDynamicSharedMemorySize, GEMM_SMEM);
    cudaFuncSetAttribute(gemm_hmma<2,1>, cudaFuncAttributeMaxDynamicSharedMemorySize, GEMM_SMEM);

    SideRes& r = side();

    // Fork first (capture-legal: s2 enters capture via an event recorded on the
    // capturing stream before any launch on s2).
    cudaEventRecord(r.evFork, 0);
    cudaStreamWaitEvent(r.s2, r.evFork, 0);

    // side: Q/P bf16 conversion.  main: Z transpose. (independent)
    convQP<<<(DIMP * KPAD + 255) / 256, 256, 0, r.s2>>>(Q, P);
    cudaEventRecord(r.evQP, r.s2);
    transpose_conv<<<dim3(CTX / 32, KPAD / 32), dim3(32, 8)>>>(Z, Zt, DIMP, CTX, KPAD);

    // side branch: PZ = P @ Z -> decay scan (needs Zt from main; Pb local to s2).
    // Record fork event AFTER transpose so s2 sees Zt.
    cudaEventRecord(r.evFork, 0);
    cudaStreamWaitEvent(r.s2, r.evFork, 0);
    gemm_hmma<0,0><<<dim3(CTX / BN, (DIMP + BM - 1) / BM), 128, GEMM_SMEM, r.s2>>>(
        Pb, KPAD, DIMP, Zt, KPAD, CTX, PZ, nullptr, CTX, CTX,
        nullptr, 0.f, DIMP, KPAD);
    decay_scan<<<DIMP, 256, 0, r.s2>>>(PZ, PZMb);
    cudaEventRecord(r.evJoin, r.s2);

    // main branch (needs Qb from s2)
    cudaStreamWaitEvent(0, r.evQP, 0);
    // 1) Wt[n][d] = sum_k Zt[n][k] * Qb[d][k]   ((QZ)^T bf16, cols>=DIMP zeroed)
    gemm_hmma<1,0><<<dim3((KPAD + BN - 1) / BN, CTX / BM), 128, GEMM_SMEM>>>(
        Zt, KPAD, CTX, Qb, KPAD, DIMP, nullptr, Wt, KPAD, DIMP,
        nullptr, 0.f, CTX, KPAD);
    // 2) Xb[m][n] = sum_k Zt[m][k] * Wt[n][k]   (= Z^T Q Z, bf16 logits)
    gemm_hmma<1,0><<<dim3(CTX / BN, CTX / BM), 128, GEMM_SMEM>>>(
        Zt, KPAD, CTX, Wt, KPAD, CTX, nullptr, Xb, CTX, CTX,
        nullptr, 0.f, CTX, KPAD);
    // 3) A = softmax(Xb), bf16 row-major
    softmax_bf16<<<CTX, 256>>>(Xb, Ab);

    // join, then final GEMM
    cudaStreamWaitEvent(0, r.evJoin, 0);
    // 4) out[d][c] = Z[d][c] + (1/N) * sum_k PZMb[d][k] * Ab[k][c]
    gemm_hmma<2,1><<<dim3(CTX / BN, (DIMP + BM - 1) / BM), 128, GEMM_SMEM>>>(
        PZMb, CTX, DIMP, Ab, CTX, CTX, out, nullptr, CTX, CTX,
        Z, 1.0f / (float)NSEQ, DIMP, CTX);
}